// round 14
// baseline (speedup 1.0000x reference)
#include <cuda_runtime.h>
#include <cuda_fp16.h>

// DAGNN: R12-champion hop structure (fp16 ping-pong, unroll-4 uniform gather,
// one warp per node) with pooling fused every 2 hops; vectorized build.
// N=100000, D=64, E=1600000, K=10.

#define MAX_N 100000
#define MAX_E 1600000
#define D 64
#define KHOPS 10
#define FULLMASK 0xffffffffu

// ---------------- device scratch (static: allocation-free rule) ----------------
__device__ __align__(256) __half g_bufA[(size_t)MAX_N * D];  // ping (12.8 MB)
__device__ __align__(256) __half g_bufB[(size_t)MAX_N * D];  // pong
__device__ float g_norm[MAX_N];      // rsqrt(max(deg,1))
__device__ float g_invn[MAX_N];      // sqrt(max(deg,1)) = 1/norm
__device__ int   g_deg[MAX_N];
__device__ int   g_cursor[MAX_N];
__device__ int   g_rowptr[MAX_N + 1];
__device__ int   g_csr_src[MAX_E];
__device__ int   g_idx64;            // 1 if src/dst are int64, 0 if int32

// ---------------- k1: init + dtype probe ----------------
__global__ void init_kernel(const void* __restrict__ dst, int n) {
    if (blockIdx.x == 0) {
        // int64 values < 2^31 have zero odd 32-bit words; int32 ids are random.
        const unsigned* w = (const unsigned*)dst;
        int ok = (w[2 * threadIdx.x + 1] == 0u) ? 1 : 0;
        int all = __syncthreads_and(ok);
        if (threadIdx.x == 0) g_idx64 = all;
    }
    for (int i = blockIdx.x * blockDim.x + threadIdx.x; i < n;
         i += gridDim.x * blockDim.x) {
        g_deg[i] = 0;
        g_cursor[i] = 0;
    }
}

// ---------------- k2: degree count (vectorized index loads) ----------------
__global__ void deg_kernel(const void* __restrict__ dst, int e) {
    int is64 = g_idx64;
    int tid = blockIdx.x * blockDim.x + threadIdx.x;
    int nth = gridDim.x * blockDim.x;
    if (!is64) {
        const int4* v = (const int4*)dst;
        int e4 = e >> 2;
        for (int i = tid; i < e4; i += nth) {
            int4 x = v[i];
            atomicAdd(&g_deg[x.x], 1);
            atomicAdd(&g_deg[x.y], 1);
            atomicAdd(&g_deg[x.z], 1);
            atomicAdd(&g_deg[x.w], 1);
        }
        for (int i = (e4 << 2) + tid; i < e; i += nth)
            atomicAdd(&g_deg[((const int*)dst)[i]], 1);
    } else {
        const longlong2* v = (const longlong2*)dst;
        int e2 = e >> 1;
        for (int i = tid; i < e2; i += nth) {
            longlong2 x = v[i];
            atomicAdd(&g_deg[(int)x.x], 1);
            atomicAdd(&g_deg[(int)x.y], 1);
        }
        for (int i = (e2 << 1) + tid; i < e; i += nth)
            atomicAdd(&g_deg[(int)((const long long*)dst)[i]], 1);
    }
}

// ---------------- k3: norm + exclusive scan (one block) ----------------
__global__ void normscan_kernel(int n) {
    __shared__ int part[1024];
    int t = threadIdx.x;
    int chunk = (n + 1023) / 1024;
    int beg = t * chunk;
    int end = beg + chunk;
    if (beg > n) beg = n;
    if (end > n) end = n;
    int s = 0;
    for (int i = beg; i < end; ++i) {
        int d = g_deg[i];
        float df = fmaxf((float)d, 1.0f);
        g_norm[i] = rsqrtf(df);
        g_invn[i] = sqrtf(df);
        s += d;
    }
    part[t] = s;
    __syncthreads();
    if (t == 0) {
        int acc = 0;
        for (int i = 0; i < 1024; ++i) { int v = part[i]; part[i] = acc; acc += v; }
    }
    __syncthreads();
    int acc = part[t];
    for (int i = beg; i < end; ++i) { g_rowptr[i] = acc; acc += g_deg[i]; }
    if (t == 1023) g_rowptr[n] = acc;
}

// ---------------- k4: CSR fill (vectorized index loads) ----------------
__device__ __forceinline__ void fill_one(int d, int sv) {
    int p = atomicAdd(&g_cursor[d], 1);
    g_csr_src[g_rowptr[d] + p] = sv;
}

__global__ void fill_kernel(const void* __restrict__ src,
                            const void* __restrict__ dst, int e) {
    int is64 = g_idx64;
    int tid = blockIdx.x * blockDim.x + threadIdx.x;
    int nth = gridDim.x * blockDim.x;
    if (!is64) {
        const int4* vd = (const int4*)dst;
        const int4* vs = (const int4*)src;
        int e4 = e >> 2;
        for (int i = tid; i < e4; i += nth) {
            int4 d = vd[i];
            int4 s = vs[i];
            fill_one(d.x, s.x);
            fill_one(d.y, s.y);
            fill_one(d.z, s.z);
            fill_one(d.w, s.w);
        }
        for (int i = (e4 << 2) + tid; i < e; i += nth)
            fill_one(((const int*)dst)[i], ((const int*)src)[i]);
    } else {
        const longlong2* vd = (const longlong2*)dst;
        const longlong2* vs = (const longlong2*)src;
        int e2 = e >> 1;
        for (int i = tid; i < e2; i += nth) {
            longlong2 d = vd[i];
            longlong2 s = vs[i];
            fill_one((int)d.x, (int)s.x);
            fill_one((int)d.y, (int)s.y);
        }
        for (int i = (e2 << 1) + tid; i < e; i += nth)
            fill_one((int)((const long long*)dst)[i],
                     (int)((const long long*)src)[i]);
    }
}

// ---------------- k5: prep: out = sig(f.s)*f, q0 = norm*f ----------------
__global__ void prep_kernel(const float* __restrict__ feat,
                            const float* __restrict__ s,
                            float* __restrict__ out,
                            __half2* __restrict__ q0, int n) {
    int warp = (blockIdx.x * blockDim.x + threadIdx.x) >> 5;
    int lane = threadIdx.x & 31;
    if (warp >= n) return;
    int base = warp * 32 + lane;
    float2 f = ((const float2*)feat)[base];
    float2 sv = ((const float2*)s)[lane];
    float dot = f.x * sv.x + f.y * sv.y;
    #pragma unroll
    for (int off = 16; off; off >>= 1) dot += __shfl_xor_sync(FULLMASK, dot, off);
    float sig = 1.0f / (1.0f + __expf(-dot));
    float2 o; o.x = sig * f.x; o.y = sig * f.y;
    ((float2*)out)[base] = o;
    float nm = g_norm[warp];
    float2 g; g.x = nm * f.x; g.y = nm * f.y;
    q0[base] = __float22half2_rn(g);
}

// ---------------- hop (odd t): q_t = norm*(norm*gather), no pooling -----------
__global__ void hop_kernel(const __half2* __restrict__ qin,
                           __half2* __restrict__ qout, int n) {
    int warp = (blockIdx.x * blockDim.x + threadIdx.x) >> 5;
    int lane = threadIdx.x & 31;
    if (warp >= n) return;
    int beg = g_rowptr[warp];
    int end = g_rowptr[warp + 1];
    float a0 = 0.0f, a1 = 0.0f;
    #pragma unroll 4
    for (int j = beg; j < end; ++j) {
        int sn = g_csr_src[j];                           // uniform (L1-hit)
        float2 v = __half22float2(qin[sn * 32 + lane]);  // 128B coalesced
        a0 += v.x; a1 += v.y;
    }
    float nm = g_norm[warp];
    float n2 = nm * nm;
    qout[warp * 32 + lane] = __float22half2_rn(make_float2(n2 * a0, n2 * a1));
}

// ---------------- hop (even t): pool h_{t-1} (own row of qin) + h_t -----------
__global__ void hop_pool2_kernel(const __half2* __restrict__ qin,
                                 __half2* __restrict__ qout,
                                 const float* __restrict__ s,
                                 float* __restrict__ out, int n) {
    int warp = (blockIdx.x * blockDim.x + threadIdx.x) >> 5;
    int lane = threadIdx.x & 31;
    if (warp >= n) return;
    int beg = g_rowptr[warp];
    int end = g_rowptr[warp + 1];
    float a0 = 0.0f, a1 = 0.0f;
    #pragma unroll 4
    for (int j = beg; j < end; ++j) {
        int sn = g_csr_src[j];
        float2 v = __half22float2(qin[sn * 32 + lane]);
        a0 += v.x; a1 += v.y;
    }
    int base = warp * 32 + lane;
    float2 sv = ((const float2*)s)[lane];
    float nm = g_norm[warp];
    float inv = g_invn[warp];

    // h_t from registers; h_{t-1} from own row of qin (hottest L2 line)
    float h0 = nm * a0, h1 = nm * a1;
    float2 p = __half22float2(qin[base]);
    float e0 = inv * p.x, e1 = inv * p.y;

    float dt = h0 * sv.x + h1 * sv.y;
    float dp = e0 * sv.x + e1 * sv.y;
    #pragma unroll
    for (int off = 16; off; off >>= 1) {
        dt += __shfl_xor_sync(FULLMASK, dt, off);
        dp += __shfl_xor_sync(FULLMASK, dp, off);
    }
    float st_ = 1.0f / (1.0f + __expf(-dt));
    float sp_ = 1.0f / (1.0f + __expf(-dp));

    qout[base] = __float22half2_rn(make_float2(nm * h0, nm * h1));

    float2* op = (float2*)out + base;
    float2 o = *op;
    o.x += st_ * h0 + sp_ * e0;
    o.y += st_ * h1 + sp_ * e1;
    *op = o;
}

// ---------------- launch ----------------
extern "C" void kernel_launch(void* const* d_in, const int* in_sizes, int n_in,
                              void* d_out, int out_size) {
    const float* feat = (const float*)d_in[0];
    const float* s    = (const float*)d_in[1];
    const void*  src  = d_in[2];
    const void*  dst  = d_in[3];
    float* out = (float*)d_out;

    int n = in_sizes[0] / D;
    int e = in_sizes[2];

    __half *dA, *dB;
    cudaGetSymbolAddress((void**)&dA, g_bufA);
    cudaGetSymbolAddress((void**)&dB, g_bufB);

    const int T = 256;
    int blkN = (n + T - 1) / T;
    int blkE = ((e >> 2) + T - 1) / T; if (blkE > 1184) blkE = 1184;
    int blkW = (int)(((size_t)n * 32 + T - 1) / T);   // one warp per node

    init_kernel<<<blkN, T>>>(dst, n);
    deg_kernel<<<blkE, T>>>(dst, e);
    normscan_kernel<<<1, 1024>>>(n);
    fill_kernel<<<blkE, T>>>(src, dst, e);
    prep_kernel<<<blkW, T>>>(feat, s, out, (__half2*)dA, n);

    __half2* qin = (__half2*)dA;
    __half2* qout = (__half2*)dB;
    for (int t = 1; t <= KHOPS; ++t) {
        if ((t & 1) == 0) {
            hop_pool2_kernel<<<blkW, T>>>(qin, qout, s, out, n);
        } else {
            hop_kernel<<<blkW, T>>>(qin, qout, n);
        }
        __half2* tmp = qin; qin = qout; qout = tmp;
    }
    (void)n_in; (void)out_size;
}

// round 16
// speedup vs baseline: 1.0935x; 1.0935x over previous
#include <cuda_runtime.h>
#include <cuda_fp16.h>

// DAGNN: R12 structure (fp16 ping-pong, fused every-hop pooling, one warp per
// node, vectorized build) + int4-batched uniform CSR index loads in the hop
// (cuts warp LDG issues/edge 2 -> 1.31; LSU-issue floor ~22 -> ~14 us).
// N=100000, D=64, E=1600000, K=10.

#define MAX_N 100000
#define MAX_E 1600000
#define D 64
#define KHOPS 10
#define FULLMASK 0xffffffffu

// ---------------- device scratch (static: allocation-free rule) ----------------
__device__ __align__(256) __half g_bufA[(size_t)MAX_N * D];  // ping (12.8 MB)
__device__ __align__(256) __half g_bufB[(size_t)MAX_N * D];  // pong
__device__ float g_norm[MAX_N];      // rsqrt(max(deg,1))
__device__ int   g_deg[MAX_N];
__device__ int   g_cursor[MAX_N];
__device__ int   g_rowptr[MAX_N + 1];
__device__ __align__(16) int g_csr_src[MAX_E];
__device__ int   g_idx64;            // 1 if src/dst are int64, 0 if int32

// ---------------- k1: init + dtype probe ----------------
__global__ void init_kernel(const void* __restrict__ dst, int n) {
    if (blockIdx.x == 0) {
        // int64 values < 2^31 have zero odd 32-bit words; int32 ids are random.
        const unsigned* w = (const unsigned*)dst;
        int ok = (w[2 * threadIdx.x + 1] == 0u) ? 1 : 0;
        int all = __syncthreads_and(ok);
        if (threadIdx.x == 0) g_idx64 = all;
    }
    for (int i = blockIdx.x * blockDim.x + threadIdx.x; i < n;
         i += gridDim.x * blockDim.x) {
        g_deg[i] = 0;
        g_cursor[i] = 0;
    }
}

// ---------------- k2: degree count (vectorized index loads) ----------------
__global__ void deg_kernel(const void* __restrict__ dst, int e) {
    int is64 = g_idx64;
    int tid = blockIdx.x * blockDim.x + threadIdx.x;
    int nth = gridDim.x * blockDim.x;
    if (!is64) {
        const int4* v = (const int4*)dst;
        int e4 = e >> 2;
        for (int i = tid; i < e4; i += nth) {
            int4 x = v[i];
            atomicAdd(&g_deg[x.x], 1);
            atomicAdd(&g_deg[x.y], 1);
            atomicAdd(&g_deg[x.z], 1);
            atomicAdd(&g_deg[x.w], 1);
        }
        for (int i = (e4 << 2) + tid; i < e; i += nth)
            atomicAdd(&g_deg[((const int*)dst)[i]], 1);
    } else {
        const longlong2* v = (const longlong2*)dst;
        int e2 = e >> 1;
        for (int i = tid; i < e2; i += nth) {
            longlong2 x = v[i];
            atomicAdd(&g_deg[(int)x.x], 1);
            atomicAdd(&g_deg[(int)x.y], 1);
        }
        for (int i = (e2 << 1) + tid; i < e; i += nth)
            atomicAdd(&g_deg[(int)((const long long*)dst)[i]], 1);
    }
}

// ---------------- k3: norm + exclusive scan (one block) ----------------
__global__ void normscan_kernel(int n) {
    __shared__ int part[1024];
    int t = threadIdx.x;
    int chunk = (n + 1023) / 1024;
    int beg = t * chunk;
    int end = beg + chunk;
    if (beg > n) beg = n;
    if (end > n) end = n;
    int s = 0;
    for (int i = beg; i < end; ++i) {
        int d = g_deg[i];
        g_norm[i] = rsqrtf(fmaxf((float)d, 1.0f));
        s += d;
    }
    part[t] = s;
    __syncthreads();
    if (t == 0) {
        int acc = 0;
        for (int i = 0; i < 1024; ++i) { int v = part[i]; part[i] = acc; acc += v; }
    }
    __syncthreads();
    int acc = part[t];
    for (int i = beg; i < end; ++i) { g_rowptr[i] = acc; acc += g_deg[i]; }
    if (t == 1023) g_rowptr[n] = acc;
}

// ---------------- k4: CSR fill (vectorized index loads) ----------------
__device__ __forceinline__ void fill_one(int d, int sv) {
    int p = atomicAdd(&g_cursor[d], 1);
    g_csr_src[g_rowptr[d] + p] = sv;
}

__global__ void fill_kernel(const void* __restrict__ src,
                            const void* __restrict__ dst, int e) {
    int is64 = g_idx64;
    int tid = blockIdx.x * blockDim.x + threadIdx.x;
    int nth = gridDim.x * blockDim.x;
    if (!is64) {
        const int4* vd = (const int4*)dst;
        const int4* vs = (const int4*)src;
        int e4 = e >> 2;
        for (int i = tid; i < e4; i += nth) {
            int4 d = vd[i];
            int4 s = vs[i];
            fill_one(d.x, s.x);
            fill_one(d.y, s.y);
            fill_one(d.z, s.z);
            fill_one(d.w, s.w);
        }
        for (int i = (e4 << 2) + tid; i < e; i += nth)
            fill_one(((const int*)dst)[i], ((const int*)src)[i]);
    } else {
        const longlong2* vd = (const longlong2*)dst;
        const longlong2* vs = (const longlong2*)src;
        int e2 = e >> 1;
        for (int i = tid; i < e2; i += nth) {
            longlong2 d = vd[i];
            longlong2 s = vs[i];
            fill_one((int)d.x, (int)s.x);
            fill_one((int)d.y, (int)s.y);
        }
        for (int i = (e2 << 1) + tid; i < e; i += nth)
            fill_one((int)((const long long*)dst)[i],
                     (int)((const long long*)src)[i]);
    }
}

// ---------------- k5: prep: out = sig(f.s)*f, q0 = norm*f ----------------
__global__ void prep_kernel(const float* __restrict__ feat,
                            const float* __restrict__ s,
                            float* __restrict__ out,
                            __half2* __restrict__ q0, int n) {
    int warp = (blockIdx.x * blockDim.x + threadIdx.x) >> 5;
    int lane = threadIdx.x & 31;
    if (warp >= n) return;
    int base = warp * 32 + lane;
    float2 f = ((const float2*)feat)[base];
    float2 sv = ((const float2*)s)[lane];
    float dot = f.x * sv.x + f.y * sv.y;
    #pragma unroll
    for (int off = 16; off; off >>= 1) dot += __shfl_xor_sync(FULLMASK, dot, off);
    float sig = 1.0f / (1.0f + __expf(-dot));
    float2 o; o.x = sig * f.x; o.y = sig * f.y;
    ((float2*)out)[base] = o;
    float nm = g_norm[warp];
    float2 g; g.x = nm * f.x; g.y = nm * f.y;
    q0[base] = __float22half2_rn(g);
}

// ---------------- hop: gather-sum with int4-batched index loads, fused pool ---
__device__ __forceinline__ void gacc(const __half2* __restrict__ qin,
                                     int sn, int lane, float& a0, float& a1) {
    float2 v = __half22float2(qin[sn * 32 + lane]);  // 128B coalesced row
    a0 += v.x; a1 += v.y;
}

__global__ void hop_kernel(const __half2* __restrict__ qin,
                           __half2* __restrict__ qout,
                           float* __restrict__ out,
                           const float* __restrict__ s, int n) {
    int warp = (blockIdx.x * blockDim.x + threadIdx.x) >> 5;
    int lane = threadIdx.x & 31;
    if (warp >= n) return;
    int beg = g_rowptr[warp];
    int end = g_rowptr[warp + 1];
    float a0 = 0.0f, a1 = 0.0f;

    int j = beg;
    // scalar head until 16B-aligned index position
    for (; j < end && (j & 3); ++j) gacc(qin, g_csr_src[j], lane, a0, a1);
    // int4-batched body: 1 uniform LDG.128 per 4 edges, 4 independent gathers
    #pragma unroll 2
    for (; j + 4 <= end; j += 4) {
        int4 s4 = *(const int4*)&g_csr_src[j];
        gacc(qin, s4.x, lane, a0, a1);
        gacc(qin, s4.y, lane, a0, a1);
        gacc(qin, s4.z, lane, a0, a1);
        gacc(qin, s4.w, lane, a0, a1);
    }
    // scalar tail
    for (; j < end; ++j) gacc(qin, g_csr_src[j], lane, a0, a1);

    float nm = g_norm[warp];
    float h0 = a0 * nm, h1 = a1 * nm;                    // h_t (fp32)
    float2 sv = ((const float2*)s)[lane];
    float dot = h0 * sv.x + h1 * sv.y;
    #pragma unroll
    for (int off = 16; off; off >>= 1) dot += __shfl_xor_sync(FULLMASK, dot, off);
    float sig = 1.0f / (1.0f + __expf(-dot));
    int base = warp * 32 + lane;
    float2* op = (float2*)out + base;
    float2 o = *op;
    o.x += sig * h0; o.y += sig * h1;
    *op = o;
    float2 g; g.x = nm * h0; g.y = nm * h1;              // q_t for next hop
    qout[base] = __float22half2_rn(g);
}

// ---------------- launch ----------------
extern "C" void kernel_launch(void* const* d_in, const int* in_sizes, int n_in,
                              void* d_out, int out_size) {
    const float* feat = (const float*)d_in[0];
    const float* s    = (const float*)d_in[1];
    const void*  src  = d_in[2];
    const void*  dst  = d_in[3];
    float* out = (float*)d_out;

    int n = in_sizes[0] / D;
    int e = in_sizes[2];

    __half *dA, *dB;
    cudaGetSymbolAddress((void**)&dA, g_bufA);
    cudaGetSymbolAddress((void**)&dB, g_bufB);

    const int T = 256;
    int blkN = (n + T - 1) / T;
    int blkE = ((e >> 2) + T - 1) / T; if (blkE > 1184) blkE = 1184;
    int blkW = (int)(((size_t)n * 32 + T - 1) / T);   // one warp per node

    init_kernel<<<blkN, T>>>(dst, n);
    deg_kernel<<<blkE, T>>>(dst, e);
    normscan_kernel<<<1, 1024>>>(n);
    fill_kernel<<<blkE, T>>>(src, dst, e);
    prep_kernel<<<blkW, T>>>(feat, s, out, (__half2*)dA, n);

    __half2* qin = (__half2*)dA;
    __half2* qout = (__half2*)dB;
    for (int t = 0; t < KHOPS; ++t) {
        hop_kernel<<<blkW, T>>>(qin, qout, out, s, n);
        __half2* tmp = qin; qin = qout; qout = tmp;
    }
    (void)n_in; (void)out_size;
}